// round 16
// baseline (speedup 1.0000x reference)
#include <cuda_runtime.h>
#include <cuda_bf16.h>
#include <cstdint>
#include <math.h>

// Problem dims (fixed by reference)
#define BB 4
#define LL 4096
#define DD 1024
#define HH 16
#define DH 64
#define MM 4096
#define NR (BB*LL)          // 16384 rows
#define NRH (NR*HH)         // 262144 head-rows

#define EPS_LN 1e-5f
#define EPS_ATTN 1e-6f

// ---------------- scratch (device globals; no allocation) ----------------
__device__ float g_bufQ[(size_t)NR*DD];
__device__ float g_bufK[(size_t)NR*DD];
__device__ float g_bufV[(size_t)NR*DD];
__device__ float g_bufPQ[(size_t)NR*DD];
__device__ float g_bufPK[(size_t)NR*DD];
__device__ float g_bufO[(size_t)NR*DD];
__device__ float g_bufA[(size_t)NR*DD];
__device__ float g_bufH[(size_t)NR*MM];      // 256 MB
__device__ float g_qg[BB*DD];
__device__ float g_alpha[(size_t)BB*HH*LL];
__device__ float g_KV[(size_t)BB*HH*DH*DH];
__device__ float g_Ksum[BB*HH*DH];

// ================= mma.sync bf16 3-pass GEMM =================
// CTA tile 128x128, BK=32, 8 warps (warp tile 32x64)
#define AROW 40                   // bf16 per A smem row (80 B, padded from 64)
#define BROW 136                  // bf16 per B smem row (272 B, padded from 256)
#define ALIMB (128*AROW*2)        // 10240 B per A limb (hi or lo)
#define BLIMB (32*BROW*2)         // 8704 B per B limb
#define STAGE (2*ALIMB + 2*BLIMB) // 37888 B
#define SMEMB (2*STAGE)           // 75776 B

__device__ __forceinline__ uint32_t smem_u32(const void* p) {
    uint32_t a;
    asm("{ .reg .u64 t; cvta.to.shared.u64 t, %1; cvt.u32.u64 %0, t; }" : "=r"(a) : "l"(p));
    return a;
}
__device__ __forceinline__ void ldsm_x4(uint32_t* r, uint32_t a) {
    asm volatile("ldmatrix.sync.aligned.m8n8.x4.shared.b16 {%0,%1,%2,%3}, [%4];"
        : "=r"(r[0]), "=r"(r[1]), "=r"(r[2]), "=r"(r[3]) : "r"(a));
}
__device__ __forceinline__ void ldsm_x4t(uint32_t* r, uint32_t a) {
    asm volatile("ldmatrix.sync.aligned.m8n8.x4.trans.shared.b16 {%0,%1,%2,%3}, [%4];"
        : "=r"(r[0]), "=r"(r[1]), "=r"(r[2]), "=r"(r[3]) : "r"(a));
}
__device__ __forceinline__ void mma_bf16(float* d, const uint32_t* a, const uint32_t* b) {
    asm volatile(
        "mma.sync.aligned.m16n8k16.row.col.f32.bf16.bf16.f32 "
        "{%0,%1,%2,%3}, {%4,%5,%6,%7}, {%8,%9}, {%0,%1,%2,%3};"
        : "+f"(d[0]), "+f"(d[1]), "+f"(d[2]), "+f"(d[3])
        : "r"(a[0]), "r"(a[1]), "r"(a[2]), "r"(a[3]), "r"(b[0]), "r"(b[1]));
}
// split fp32 -> bf16 hi + bf16 lo, pack pairs into b32
__device__ __forceinline__ void split_pack(float x, float y, uint32_t &h, uint32_t &l) {
    __nv_bfloat16 hx = __float2bfloat16(x), hy = __float2bfloat16(y);
    float rx = x - __bfloat162float(hx), ry = y - __bfloat162float(hy);
    __nv_bfloat16 lx = __float2bfloat16(rx), ly = __float2bfloat16(ry);
    h = (uint32_t)__bfloat16_as_ushort(hx) | ((uint32_t)__bfloat16_as_ushort(hy) << 16);
    l = (uint32_t)__bfloat16_as_ushort(lx) | ((uint32_t)__bfloat16_as_ushort(ly) << 16);
}
__device__ __forceinline__ float gelu_exact(float x) {
    return 0.5f * x * (1.0f + erff(x * 0.7071067811865476f));
}

// C[MR,Ntot] = A[MR,Ktot] @ W[Ktot,Ntot]
// epi 0: +bias   epi 1: gelu(+bias)   epi 2: +bias+res1+res2
__global__ __launch_bounds__(256, 1) void tc_gemm_k(
    const float* __restrict__ A, const float* __restrict__ W,
    const float* __restrict__ bias, const float* __restrict__ res1,
    const float* __restrict__ res2, float* __restrict__ C,
    int Ntot, int Ktot, int epi)
{
    extern __shared__ char smem[];
    uint32_t sb = smem_u32(smem);
    int tid = threadIdx.x, wid = tid >> 5, lane = tid & 31;
    int mw = wid & 3, nw = wid >> 2;            // warp tile: rows mw*32, cols nw*64

    const float* Ab = A + (size_t)(blockIdx.y * 128) * Ktot;
    const float* Wb = W + (size_t)blockIdx.x * 128;

    float acc[2][8][4];
    #pragma unroll
    for (int i = 0; i < 2; i++)
        #pragma unroll
        for (int j = 0; j < 8; j++)
            #pragma unroll
            for (int e = 0; e < 4; e++) acc[i][j][e] = 0.f;

    float a_reg[16], b_reg[16];

    const int T = Ktot / 32;

    // ---- prologue: load tile 0 ----
    #pragma unroll
    for (int j = 0; j < 4; j++) {
        int idx = j * 256 + tid;
        *(float4*)&a_reg[j*4] = *(const float4*)(Ab + (size_t)(idx >> 3) * Ktot + (idx & 7) * 4);
        int r = (j * 256 + tid) >> 5, c4 = (j * 256 + tid) & 31;
        *(float4*)&b_reg[j*4] = *(const float4*)(Wb + (size_t)r * Ntot + c4 * 4);
    }
    {
        char* st = smem;
        #pragma unroll
        for (int j = 0; j < 4; j++) {
            int idx = j * 256 + tid;
            int r = idx >> 3, c4 = idx & 7;
            uint32_t h0, l0, h1, l1;
            split_pack(a_reg[j*4+0], a_reg[j*4+1], h0, l0);
            split_pack(a_reg[j*4+2], a_reg[j*4+3], h1, l1);
            uint32_t off = (uint32_t)(r * 80 + c4 * 8);
            *(uint2*)(st + off)         = make_uint2(h0, h1);
            *(uint2*)(st + ALIMB + off) = make_uint2(l0, l1);
            int rb = idx >> 5, cb = idx & 31;
            split_pack(b_reg[j*4+0], b_reg[j*4+1], h0, l0);
            split_pack(b_reg[j*4+2], b_reg[j*4+3], h1, l1);
            uint32_t offb = (uint32_t)(rb * 272 + cb * 8);
            *(uint2*)(st + 2*ALIMB + offb)         = make_uint2(h0, h1);
            *(uint2*)(st + 2*ALIMB + BLIMB + offb) = make_uint2(l0, l1);
        }
    }
    __syncthreads();

    for (int t = 0; t < T; t++) {
        int s = t & 1;
        // ---- prefetch next tile into regs ----
        if (t + 1 < T) {
            int kt = (t + 1) * 32;
            #pragma unroll
            for (int j = 0; j < 4; j++) {
                int idx = j * 256 + tid;
                *(float4*)&a_reg[j*4] = *(const float4*)(Ab + (size_t)(idx >> 3) * Ktot + kt + (idx & 7) * 4);
                int r = idx >> 5, c4 = idx & 31;
                *(float4*)&b_reg[j*4] = *(const float4*)(Wb + (size_t)(kt + r) * Ntot + c4 * 4);
            }
        }
        // ---- compute current stage ----
        uint32_t Abase = sb + (uint32_t)s * STAGE;
        uint32_t Bbase = Abase + 2 * ALIMB;
        #pragma unroll
        for (int kk = 0; kk < 2; kk++) {           // two k16 steps
            uint32_t ah[2][4], al[2][4], bh[8][2], bl[8][2];
            #pragma unroll
            for (int mi = 0; mi < 2; mi++) {
                uint32_t ad = Abase + (uint32_t)((mw*32 + mi*16 + (lane & 15)) * 80
                                               + (kk*2 + (lane >> 4)) * 16);
                ldsm_x4(ah[mi], ad);
                ldsm_x4(al[mi], ad + ALIMB);
            }
            #pragma unroll
            for (int nj = 0; nj < 4; nj++) {       // pairs of n8 tiles
                uint32_t bd = Bbase + (uint32_t)((kk*16 + (lane & 15)) * 272
                                               + (nw*8 + nj*2 + (lane >> 4)) * 16);
                uint32_t rh[4], rl[4];
                ldsm_x4t(rh, bd);
                ldsm_x4t(rl, bd + BLIMB);
                bh[2*nj][0] = rh[0]; bh[2*nj][1] = rh[1];
                bh[2*nj+1][0] = rh[2]; bh[2*nj+1][1] = rh[3];
                bl[2*nj][0] = rl[0]; bl[2*nj][1] = rl[1];
                bl[2*nj+1][0] = rl[2]; bl[2*nj+1][1] = rl[3];
            }
            // pass-major: dependent MMAs on same acc separated by 15 others
            #pragma unroll
            for (int mi = 0; mi < 2; mi++)
                #pragma unroll
                for (int ni = 0; ni < 8; ni++) mma_bf16(acc[mi][ni], ah[mi], bh[ni]);
            #pragma unroll
            for (int mi = 0; mi < 2; mi++)
                #pragma unroll
                for (int ni = 0; ni < 8; ni++) mma_bf16(acc[mi][ni], al[mi], bh[ni]);
            #pragma unroll
            for (int mi = 0; mi < 2; mi++)
                #pragma unroll
                for (int ni = 0; ni < 8; ni++) mma_bf16(acc[mi][ni], ah[mi], bl[ni]);
        }
        // ---- store prefetched tile into the other stage ----
        if (t + 1 < T) {
            char* st = smem + ((t + 1) & 1) * STAGE;
            #pragma unroll
            for (int j = 0; j < 4; j++) {
                int idx = j * 256 + tid;
                int r = idx >> 3, c4 = idx & 7;
                uint32_t h0, l0, h1, l1;
                split_pack(a_reg[j*4+0], a_reg[j*4+1], h0, l0);
                split_pack(a_reg[j*4+2], a_reg[j*4+3], h1, l1);
                uint32_t off = (uint32_t)(r * 80 + c4 * 8);
                *(uint2*)(st + off)         = make_uint2(h0, h1);
                *(uint2*)(st + ALIMB + off) = make_uint2(l0, l1);
                int rb = idx >> 5, cb = idx & 31;
                split_pack(b_reg[j*4+0], b_reg[j*4+1], h0, l0);
                split_pack(b_reg[j*4+2], b_reg[j*4+3], h1, l1);
                uint32_t offb = (uint32_t)(rb * 272 + cb * 8);
                *(uint2*)(st + 2*ALIMB + offb)         = make_uint2(h0, h1);
                *(uint2*)(st + 2*ALIMB + BLIMB + offb) = make_uint2(l0, l1);
            }
        }
        __syncthreads();
    }

    // ---- epilogue ----
    #pragma unroll
    for (int mi = 0; mi < 2; mi++) {
        #pragma unroll
        for (int ni = 0; ni < 8; ni++) {
            int r0 = blockIdx.y * 128 + mw * 32 + mi * 16 + (lane >> 2);
            int c  = blockIdx.x * 128 + nw * 64 + ni * 8 + (lane & 3) * 2;
            float2 bv = *(const float2*)(bias + c);
            #pragma unroll
            for (int half = 0; half < 2; half++) {
                int row = r0 + half * 8;
                float vx = acc[mi][ni][half * 2 + 0] + bv.x;
                float vy = acc[mi][ni][half * 2 + 1] + bv.y;
                if (epi == 1) {
                    vx = gelu_exact(vx);
                    vy = gelu_exact(vy);
                } else if (epi == 2) {
                    size_t idx = (size_t)row * Ntot + c;
                    float2 r1 = *(const float2*)(res1 + idx);
                    float2 r2 = *(const float2*)(res2 + idx);
                    vx += r1.x + r2.x;
                    vy += r1.y + r2.y;
                }
                *(float2*)(C + (size_t)row * Ntot + c) = make_float2(vx, vy);
            }
        }
    }
}

// ---------------- block reduction helpers (blockDim.x == 256) ----------------
__device__ __forceinline__ float blockSum256(float v, float* sm) {
    #pragma unroll
    for (int o = 16; o; o >>= 1) v += __shfl_xor_sync(0xffffffffu, v, o);
    int t = threadIdx.x;
    __syncthreads();
    if ((t & 31) == 0) sm[t >> 5] = v;
    __syncthreads();
    if (t == 0) {
        float z = 0.f;
        #pragma unroll
        for (int i = 0; i < 8; i++) z += sm[i];
        sm[8] = z;
    }
    __syncthreads();
    return sm[8];
}
__device__ __forceinline__ float blockMax256(float v, float* sm) {
    #pragma unroll
    for (int o = 16; o; o >>= 1) v = fmaxf(v, __shfl_xor_sync(0xffffffffu, v, o));
    int t = threadIdx.x;
    __syncthreads();
    if ((t & 31) == 0) sm[t >> 5] = v;
    __syncthreads();
    if (t == 0) {
        float z = sm[0];
        #pragma unroll
        for (int i = 1; i < 8; i++) z = fmaxf(z, sm[i]);
        sm[8] = z;
    }
    __syncthreads();
    return sm[8];
}

// ---------------- LayerNorm over 1024, one row per block ----------------
__global__ void ln1024_k(const float* __restrict__ X, float* __restrict__ Y,
                         const float* __restrict__ g, const float* __restrict__ bta)
{
    __shared__ float sm[9];
    size_t row = blockIdx.x;
    int t = threadIdx.x;
    const float* xr = X + row * 1024;
    float4 v = *(const float4*)(xr + t * 4);
    float s = v.x + v.y + v.z + v.w;
    float mean = blockSum256(s, sm) * (1.0f / 1024.0f);
    float dx = v.x - mean, dy = v.y - mean, dz = v.z - mean, dw = v.w - mean;
    float q = dx * dx + dy * dy + dz * dz + dw * dw;
    float var = blockSum256(q, sm) * (1.0f / 1024.0f);
    float rstd = rsqrtf(var + EPS_LN);
    int c = t * 4;
    float4 gg = *(const float4*)(g + c);
    float4 bb = *(const float4*)(bta + c);
    float4 o;
    o.x = dx * rstd * gg.x + bb.x;
    o.y = dy * rstd * gg.y + bb.y;
    o.z = dz * rstd * gg.z + bb.z;
    o.w = dw * rstd * gg.w + bb.w;
    *(float4*)(Y + row * 1024 + c) = o;
}

// ---------------- phi feature map ----------------
__device__ __forceinline__ float phi_map(float x, float cc) {
    float z = -x * cc;
    float sp = (z > 20.0f) ? z : log1pf(expf(z));
    return sp / cc + x;
}

__global__ void phi_k(const float* __restrict__ T, float* __restrict__ P,
                      const float* __restrict__ Wg, const float* __restrict__ bg,
                      const float* __restrict__ gg, const float* __restrict__ betag,
                      const float* __restrict__ cptr)
{
    __shared__ float Ws[64 * 64];
    __shared__ float sbg[64], sgg[64], sbeta[64];
    int t = threadIdx.x;
    for (int i = t; i < 4096; i += 256) Ws[i] = Wg[i];
    if (t < 64) { sbg[t] = bg[t]; sgg[t] = gg[t]; sbeta[t] = betag[t]; }
    __syncthreads();

    float cc = fabsf(*cptr) + EPS_ATTN;
    int w = t >> 5, lane = t & 31;
    size_t row = (size_t)blockIdx.x * 8 + w;
    const float* tr = T + row * 64;
    float t0 = tr[lane], t1 = tr[32 + lane];

    float u0 = sbg[lane], u1 = sbg[32 + lane];
    #pragma unroll
    for (int dd = 0; dd < 32; dd++) {
        float a0 = __shfl_sync(0xffffffffu, t0, dd);
        float a1 = __shfl_sync(0xffffffffu, t1, dd);
        u0 += a0 * Ws[dd * 64 + lane]        + a1 * Ws[(dd + 32) * 64 + lane];
        u1 += a0 * Ws[dd * 64 + lane + 32]   + a1 * Ws[(dd + 32) * 64 + lane + 32];
    }
    float s = u0 + u1;
    #pragma unroll
    for (int o = 16; o; o >>= 1) s += __shfl_xor_sync(0xffffffffu, s, o);
    float mean = s * (1.0f / 64.0f);
    float d0 = u0 - mean, d1 = u1 - mean;
    float q = d0 * d0 + d1 * d1;
    #pragma unroll
    for (int o = 16; o; o >>= 1) q += __shfl_xor_sync(0xffffffffu, q, o);
    float rstd = rsqrtf(q * (1.0f / 64.0f) + EPS_LN);
    float x0 = d0 * rstd * sgg[lane]      + sbeta[lane];
    float x1 = d1 * rstd * sgg[32 + lane] + sbeta[32 + lane];
    P[row * 64 + lane]      = phi_map(x0, cc);
    P[row * 64 + 32 + lane] = phi_map(x1, cc);
}

// ---------------- misc ----------------
__global__ void zero_k(float* __restrict__ p, int n) {
    int i = blockIdx.x * 256 + threadIdx.x;
    if (i < n) p[i] = 0.0f;
}

__global__ void qgsum_k(const float* __restrict__ Q, float* __restrict__ qg)
{
    int j = blockIdx.x * 32 + threadIdx.x;
    int b = blockIdx.y;
    int l0 = blockIdx.z * 512 + threadIdx.y;
    const float* base = Q + ((size_t)b * LL + l0) * DD + j;
    float s = 0.f;
    #pragma unroll 8
    for (int i = 0; i < 64; i++) s += base[(size_t)i * 8 * DD];
    __shared__ float sm[8][32];
    sm[threadIdx.y][threadIdx.x] = s;
    __syncthreads();
    if (threadIdx.y == 0) {
        float tot = 0.f;
        #pragma unroll
        for (int r = 0; r < 8; r++) tot += sm[r][threadIdx.x];
        atomicAdd(&qg[b * DD + j], tot * (1.0f / 32768.0f));
    }
}

__global__ void scores_k(const float* __restrict__ Kln, const float* __restrict__ qg,
                         float* __restrict__ sc)
{
    int t = threadIdx.x, w = t >> 5, lane = t & 31;
    size_t r = (size_t)blockIdx.x * 8 + w;
    int h = (int)(r & 15);
    size_t bl = r >> 4;
    int l = (int)(bl & 4095);
    int b = (int)(bl >> 12);
    const float* kr = Kln + r * 64;
    const float* qr = qg + b * DD + h * 64;
    float s = kr[lane] * qr[lane] + kr[lane + 32] * qr[lane + 32];
    #pragma unroll
    for (int o = 16; o; o >>= 1) s += __shfl_xor_sync(0xffffffffu, s, o);
    if (lane == 0) sc[(size_t)(b * HH + h) * LL + l] = s;
}

__global__ void softmax_k(float* __restrict__ sc)
{
    __shared__ float sm[9];
    size_t base = (size_t)blockIdx.x * LL;
    int t = threadIdx.x;
    float v[16];
    const float4* p = (const float4*)(sc + base + t * 16);
    #pragma unroll
    for (int i = 0; i < 4; i++) {
        float4 a = p[i];
        v[i * 4 + 0] = a.x; v[i * 4 + 1] = a.y; v[i * 4 + 2] = a.z; v[i * 4 + 3] = a.w;
    }
    float m = v[0];
    #pragma unroll
    for (int i = 1; i < 16; i++) m = fmaxf(m, v[i]);
    m = blockMax256(m, sm);
    float s = 0.f;
    #pragma unroll
    for (int i = 0; i < 16; i++) { v[i] = expf(v[i] - m); s += v[i]; }
    s = blockSum256(s, sm);
    float inv = (float)LL / s;
    float4* po = (float4*)(sc + base + t * 16);
    #pragma unroll
    for (int i = 0; i < 4; i++) {
        float4 a;
        a.x = v[i * 4 + 0] * inv; a.y = v[i * 4 + 1] * inv;
        a.z = v[i * 4 + 2] * inv; a.w = v[i * 4 + 3] * inv;
        po[i] = a;
    }
}

__global__ void kv_k(const float* __restrict__ PK, const float* __restrict__ Vln,
                     const float* __restrict__ alpha, float* __restrict__ KV,
                     float* __restrict__ Ksum)
{
    __shared__ float kk[16][64];
    __shared__ float vv[16][64];
    int bh = blockIdx.x;
    int b = bh >> 4, h = bh & 15;
    int t = threadIdx.x;
    int lr = t >> 4;
    int c4 = (t & 15) * 4;
    int r4 = lr * 4;
    float acc[4][4];
    float ks[4] = {0.f, 0.f, 0.f, 0.f};
    #pragma unroll
    for (int i = 0; i < 4; i++)
        #pragma unroll
        for (int j = 0; j < 4; j++) acc[i][j] = 0.f;

    const float* aB = alpha + (size_t)bh * LL;
    int lstart = blockIdx.y * 512;
    for (int lc = lstart; lc < lstart + 512; lc += 16) {
        int l = lc + lr;
        size_t r = ((size_t)(b * LL + l) * HH + h);
        float al = aB[l];
        float4 k4 = *(const float4*)(PK + r * 64 + c4);
        k4.x *= al; k4.y *= al; k4.z *= al; k4.w *= al;
        *(float4*)&kk[lr][c4] = k4;
        *(float4*)&vv[lr][c4] = *(const float4*)(Vln + r * 64 + c4);
        __syncthreads();
        #pragma unroll
        for (int q = 0; q < 16; q++) {
            float4 ka = *(const float4*)&kk[q][r4];
            float4 vb = *(const float4*)&vv[q][c4];
            acc[0][0] += ka.x * vb.x; acc[0][1] += ka.x * vb.y; acc[0][2] += ka.x * vb.z; acc[0][3] += ka.x * vb.w;
            acc[1][0] += ka.y * vb.x; acc[1][1] += ka.y * vb.y; acc[1][2] += ka.y * vb.z; acc[1][3] += ka.y * vb.w;
            acc[2][0] += ka.z * vb.x; acc[2][1] += ka.z * vb.y; acc[2][2] += ka.z * vb.z; acc[2][3] += ka.z * vb.w;
            acc[3][0] += ka.w * vb.x; acc[3][1] += ka.w * vb.y; acc[3][2] += ka.w * vb.z; acc[3][3] += ka.w * vb.w;
            if (c4 == 0) { ks[0] += ka.x; ks[1] += ka.y; ks[2] += ka.z; ks[3] += ka.w; }
        }
        __syncthreads();
    }
    float* KVb = KV + (size_t)bh * 4096;
    #pragma unroll
    for (int i = 0; i < 4; i++)
        #pragma unroll
        for (int j = 0; j < 4; j++)
            atomicAdd(&KVb[(r4 + i) * 64 + c4 + j], acc[i][j]);
    if (c4 == 0) {
        #pragma unroll
        for (int i = 0; i < 4; i++) atomicAdd(&Ksum[bh * 64 + r4 + i], ks[i]);
    }
}

__global__ void out_k(const float* __restrict__ PQ, const float* __restrict__ KV,
                      const float* __restrict__ Ksum, float* __restrict__ O)
{
    __shared__ float KVs[64 * 64];
    __shared__ float Ks[64];
    int bh = blockIdx.x;
    int b = bh >> 4, h = bh & 15;
    int t = threadIdx.x, w = t >> 5, lane = t & 31;
    const float* KVg = KV + (size_t)bh * 4096;
    for (int i = t; i < 1024; i += 256)
        *(float4*)&KVs[i * 4] = *(const float4*)&KVg[i * 4];
    if (t < 64) Ks[t] = Ksum[bh * 64 + t];
    __syncthreads();

    int l0 = blockIdx.y * 8 + w;
    for (int it = 0; it < 64; it++) {
        int l = l0 + it * 64;
        size_t r = ((size_t)(b * LL + l) * HH + h);
        const float* q = PQ + r * 64;
        float q0 = q[lane], q1 = q[lane + 32];
        float dpart = q0 * Ks[lane] + q1 * Ks[lane + 32];
        #pragma unroll
        for (int o = 16; o; o >>= 1) dpart += __shfl_xor_sync(0xffffffffu, dpart, o);
        float n0 = 0.f, n1 = 0.f;
        #pragma unroll
        for (int dd = 0; dd < 32; dd++) {
            float a0 = __shfl_sync(0xffffffffu, q0, dd);
            float a1 = __shfl_sync(0xffffffffu, q1, dd);
            n0 += a0 * KVs[dd * 64 + lane]        + a1 * KVs[(dd + 32) * 64 + lane];
            n1 += a0 * KVs[dd * 64 + lane + 32]   + a1 * KVs[(dd + 32) * 64 + lane + 32];
        }
        float inv = 1.0f / (dpart + EPS_ATTN);
        O[r * 64 + lane]      = n0 * inv;
        O[r * 64 + lane + 32] = n1 * inv;
    }
}

// ---------------- launch ----------------
extern "C" void kernel_launch(void* const* d_in, const int* in_sizes, int n_in,
                              void* d_out, int out_size)
{
    (void)in_sizes; (void)n_in; (void)out_size;
    const float* x     = (const float*)d_in[0];
    const float* WQ    = (const float*)d_in[1];
    const float* bQ    = (const float*)d_in[2];
    const float* gQ    = (const float*)d_in[3];
    const float* betaQ = (const float*)d_in[4];
    const float* WK    = (const float*)d_in[5];
    const float* bK    = (const float*)d_in[6];
    const float* gK    = (const float*)d_in[7];
    const float* betaK = (const float*)d_in[8];
    const float* WV    = (const float*)d_in[9];
    const float* bV    = (const float*)d_in[10];
    const float* gV    = (const float*)d_in[11];
    const float* betaV = (const float*)d_in[12];
    const float* Wg    = (const float*)d_in[13];
    const float* bg    = (const float*)d_in[14];
    const float* gg    = (const float*)d_in[15];
    const float* betag = (const float*)d_in[16];
    const float* cpt   = (const float*)d_in[17];
    const float* g_an  = (const float*)d_in[18];
    const float* b_an  = (const float*)d_in[19];
    const float* W1    = (const float*)d_in[20];
    const float* b1    = (const float*)d_in[21];
    const float* W2    = (const float*)d_in[22];
    const float* b2    = (const float*)d_in[23];
    float* out = (float*)d_out;

    float *bufQ, *bufK, *bufV, *bufPQ, *bufPK, *bufO, *bufA, *bufH;
    float *qg, *alpha, *KV, *Ksum;
    cudaGetSymbolAddress((void**)&bufQ,  g_bufQ);
    cudaGetSymbolAddress((void**)&bufK,  g_bufK);
    cudaGetSymbolAddress((void**)&bufV,  g_bufV);
    cudaGetSymbolAddress((void**)&bufPQ, g_bufPQ);
    cudaGetSymbolAddress((void**)&bufPK, g_bufPK);
    cudaGetSymbolAddress((void**)&bufO,  g_bufO);
    cudaGetSymbolAddress((void**)&bufA,  g_bufA);
    cudaGetSymbolAddress((void**)&bufH,  g_bufH);
    cudaGetSymbolAddress((void**)&qg,    g_qg);
    cudaGetSymbolAddress((void**)&alpha, g_alpha);
    cudaGetSymbolAddress((void**)&KV,    g_KV);
    cudaGetSymbolAddress((void**)&Ksum,  g_Ksum);

    cudaFuncSetAttribute(tc_gemm_k, cudaFuncAttributeMaxDynamicSharedMemorySize, SMEMB);

    dim3 gq(DD / 128, NR / 128);          // (8,128)
    tc_gemm_k<<<gq, 256, SMEMB>>>(x, WQ, bQ, nullptr, nullptr, bufQ, DD, DD, 0);
    tc_gemm_k<<<gq, 256, SMEMB>>>(x, WK, bK, nullptr, nullptr, bufK, DD, DD, 0);
    tc_gemm_k<<<gq, 256, SMEMB>>>(x, WV, bV, nullptr, nullptr, bufV, DD, DD, 0);

    ln1024_k<<<NR, 256>>>(bufQ, bufQ, gQ, betaQ);
    ln1024_k<<<NR, 256>>>(bufK, bufK, gK, betaK);
    ln1024_k<<<NR, 256>>>(bufV, bufV, gV, betaV);

    phi_k<<<NRH / 8, 256>>>(bufQ, bufPQ, Wg, bg, gg, betag, cpt);
    phi_k<<<NRH / 8, 256>>>(bufK, bufPK, Wg, bg, gg, betag, cpt);

    zero_k<<<(BB * DD + 255) / 256, 256>>>(qg, BB * DD);
    qgsum_k<<<dim3(DD / 32, BB, LL / 512), dim3(32, 8)>>>(bufQ, qg);

    scores_k<<<NRH / 8, 256>>>(bufK, qg, alpha);
    softmax_k<<<BB * HH, 256>>>(alpha);

    zero_k<<<(BB * HH * DH * DH + 255) / 256, 256>>>(KV, BB * HH * DH * DH);
    zero_k<<<(BB * HH * DH + 255) / 256, 256>>>(Ksum, BB * HH * DH);
    kv_k<<<dim3(BB * HH, 8), 256>>>(bufPK, bufV, alpha, KV, Ksum);

    out_k<<<dim3(BB * HH, 8), 256>>>(bufPQ, KV, Ksum, bufO);
    ln1024_k<<<NR, 256>>>(bufO, bufA, g_an, b_an);

    tc_gemm_k<<<dim3(MM / 128, NR / 128), 256, SMEMB>>>(bufA, W1, b1, nullptr, nullptr, bufH, MM, DD, 1);
    tc_gemm_k<<<dim3(DD / 128, NR / 128), 256, SMEMB>>>(bufH, W2, b2, bufA, x, out, DD, MM, 2);
}

// round 17
// speedup vs baseline: 1.2945x; 1.2945x over previous
#include <cuda_runtime.h>
#include <cuda_bf16.h>
#include <cstdint>
#include <math.h>

// Problem dims (fixed by reference)
#define BB 4
#define LL 4096
#define DD 1024
#define HH 16
#define DH 64
#define MM 4096
#define NR (BB*LL)          // 16384 rows
#define NRH (NR*HH)         // 262144 head-rows

#define EPS_LN 1e-5f
#define EPS_ATTN 1e-6f

// ---------------- scratch (device globals; no allocation) ----------------
__device__ float g_bufQ[(size_t)NR*DD];
__device__ float g_bufK[(size_t)NR*DD];
__device__ float g_bufV[(size_t)NR*DD];
__device__ float g_bufPQ[(size_t)NR*DD];
__device__ float g_bufPK[(size_t)NR*DD];
__device__ float g_bufO[(size_t)NR*DD];
__device__ float g_bufA[(size_t)NR*DD];
__device__ float g_qg[BB*DD];
__device__ float g_alpha[(size_t)BB*HH*LL];
__device__ float g_KV[(size_t)BB*HH*DH*DH];
__device__ float g_Ksum[BB*HH*DH];

// bf16 hi/lo planes
__device__ __nv_bfloat16 g_xh[(size_t)NR*DD],  g_xl[(size_t)NR*DD];
__device__ __nv_bfloat16 g_Ah[(size_t)NR*DD],  g_Al[(size_t)NR*DD];
__device__ __nv_bfloat16 g_Hh[(size_t)NR*MM],  g_Hl[(size_t)NR*MM];   // 128MB each
__device__ __nv_bfloat16 g_WQh[(size_t)DD*DD], g_WQl[(size_t)DD*DD];
__device__ __nv_bfloat16 g_WKh[(size_t)DD*DD], g_WKl[(size_t)DD*DD];
__device__ __nv_bfloat16 g_WVh[(size_t)DD*DD], g_WVl[(size_t)DD*DD];
__device__ __nv_bfloat16 g_W1h[(size_t)DD*MM], g_W1l[(size_t)DD*MM];
__device__ __nv_bfloat16 g_W2h[(size_t)MM*DD], g_W2l[(size_t)MM*DD];

// ================= mma.sync bf16 3-pass GEMM (pre-split operands) =========
// CTA tile 128x128, BK=32, 8 warps (warp tile 32x64), cp.async double buffer
#define ALIMB (128*80)            // 10240 B per A limb (80 B padded rows)
#define BLIMB (32*272)            // 8704 B per B limb (272 B padded rows)
#define STAGE (2*ALIMB + 2*BLIMB) // 37888 B
#define SMEMB (2*STAGE)           // 75776 B

__device__ __forceinline__ uint32_t smem_u32(const void* p) {
    uint32_t a;
    asm("{ .reg .u64 t; cvta.to.shared.u64 t, %1; cvt.u32.u64 %0, t; }" : "=r"(a) : "l"(p));
    return a;
}
__device__ __forceinline__ void cp16(uint32_t dst, const void* src) {
    asm volatile("cp.async.cg.shared.global [%0], [%1], 16;" :: "r"(dst), "l"(src));
}
__device__ __forceinline__ void ldsm_x4(uint32_t* r, uint32_t a) {
    asm volatile("ldmatrix.sync.aligned.m8n8.x4.shared.b16 {%0,%1,%2,%3}, [%4];"
        : "=r"(r[0]), "=r"(r[1]), "=r"(r[2]), "=r"(r[3]) : "r"(a));
}
__device__ __forceinline__ void ldsm_x4t(uint32_t* r, uint32_t a) {
    asm volatile("ldmatrix.sync.aligned.m8n8.x4.trans.shared.b16 {%0,%1,%2,%3}, [%4];"
        : "=r"(r[0]), "=r"(r[1]), "=r"(r[2]), "=r"(r[3]) : "r"(a));
}
__device__ __forceinline__ void mma_bf16(float* d, const uint32_t* a, const uint32_t* b) {
    asm volatile(
        "mma.sync.aligned.m16n8k16.row.col.f32.bf16.bf16.f32 "
        "{%0,%1,%2,%3}, {%4,%5,%6,%7}, {%8,%9}, {%0,%1,%2,%3};"
        : "+f"(d[0]), "+f"(d[1]), "+f"(d[2]), "+f"(d[3])
        : "r"(a[0]), "r"(a[1]), "r"(a[2]), "r"(a[3]), "r"(b[0]), "r"(b[1]));
}
// split fp32 -> bf16 hi + bf16 lo, pack pairs into b32
__device__ __forceinline__ void split_pack(float x, float y, uint32_t &h, uint32_t &l) {
    __nv_bfloat16 hx = __float2bfloat16(x), hy = __float2bfloat16(y);
    float rx = x - __bfloat162float(hx), ry = y - __bfloat162float(hy);
    __nv_bfloat16 lx = __float2bfloat16(rx), ly = __float2bfloat16(ry);
    h = (uint32_t)__bfloat16_as_ushort(hx) | ((uint32_t)__bfloat16_as_ushort(hy) << 16);
    l = (uint32_t)__bfloat16_as_ushort(lx) | ((uint32_t)__bfloat16_as_ushort(ly) << 16);
}
__device__ __forceinline__ float gelu_exact(float x) {
    return 0.5f * x * (1.0f + erff(x * 0.7071067811865476f));
}

// ---- standalone split: X[i] -> H[i] + L[i] (grid = n/1024, block 256) ----
__global__ void split_k(const float* __restrict__ X, __nv_bfloat16* __restrict__ H,
                        __nv_bfloat16* __restrict__ L)
{
    size_t i = ((size_t)blockIdx.x * 256 + threadIdx.x) * 4;
    float4 v = *(const float4*)(X + i);
    uint32_t h0, l0, h1, l1;
    split_pack(v.x, v.y, h0, l0);
    split_pack(v.z, v.w, h1, l1);
    *(uint2*)(H + i) = make_uint2(h0, h1);
    *(uint2*)(L + i) = make_uint2(l0, l1);
}

// C[MR,Ntot] = A[MR,Ktot] @ W[Ktot,Ntot], operands pre-split bf16 hi/lo planes
// epi 0: C = acc+bias (fp32)
// epi 1: gelu(acc+bias) -> Ch/Cl bf16 planes (no fp32 output)
// epi 2: C = acc+bias+res1+res2 (fp32)
__global__ __launch_bounds__(256, 2) void tc_gemm_k(
    const __nv_bfloat16* __restrict__ Ah, const __nv_bfloat16* __restrict__ Al,
    const __nv_bfloat16* __restrict__ Bh, const __nv_bfloat16* __restrict__ Bl,
    const float* __restrict__ bias, const float* __restrict__ res1,
    const float* __restrict__ res2, float* __restrict__ C,
    __nv_bfloat16* __restrict__ Ch, __nv_bfloat16* __restrict__ Cl,
    int Ntot, int Ktot, int epi)
{
    extern __shared__ char smem[];
    uint32_t sb = smem_u32(smem);
    int tid = threadIdx.x, wid = tid >> 5, lane = tid & 31;
    int mw = wid & 3, nw = wid >> 2;

    const __nv_bfloat16* Abh = Ah + (size_t)(blockIdx.y * 128) * Ktot;
    const __nv_bfloat16* Abl = Al + (size_t)(blockIdx.y * 128) * Ktot;
    const __nv_bfloat16* Bbh = Bh + (size_t)blockIdx.x * 128;
    const __nv_bfloat16* Bbl = Bl + (size_t)blockIdx.x * 128;

    float acc[2][8][4];
    #pragma unroll
    for (int i = 0; i < 2; i++)
        #pragma unroll
        for (int j = 0; j < 8; j++)
            #pragma unroll
            for (int e = 0; e < 4; e++) acc[i][j][e] = 0.f;

    const int T = Ktot / 32;

    // ---- stage loader: 8 cp.async of 16B per thread ----
    auto load_stage = [&](int t) {
        uint32_t st = sb + (uint32_t)(t & 1) * STAGE;
        int kt = t * 32;
        #pragma unroll
        for (int j = 0; j < 2; j++) {
            int idx = j * 256 + tid;
            int r = idx >> 2, ck = idx & 3;              // A: 128 rows x 4 chunks
            uint32_t d = st + (uint32_t)(r * 80 + ck * 16);
            const __nv_bfloat16* s = Abh + (size_t)r * Ktot + kt + ck * 8;
            cp16(d, s);
            cp16(d + ALIMB, Abl + (size_t)r * Ktot + kt + ck * 8);
        }
        #pragma unroll
        for (int j = 0; j < 2; j++) {
            int idx = j * 256 + tid;
            int r = idx >> 4, ck = idx & 15;             // B: 32 rows x 16 chunks
            uint32_t d = st + 2*ALIMB + (uint32_t)(r * 272 + ck * 16);
            cp16(d, Bbh + (size_t)(kt + r) * Ntot + ck * 8);
            cp16(d + BLIMB, Bbl + (size_t)(kt + r) * Ntot + ck * 8);
        }
        asm volatile("cp.async.commit_group;" ::: "memory");
    };

    load_stage(0);

    for (int t = 0; t < T; t++) {
        if (t + 1 < T) {
            load_stage(t + 1);
            asm volatile("cp.async.wait_group 1;" ::: "memory");
        } else {
            asm volatile("cp.async.wait_group 0;" ::: "memory");
        }
        __syncthreads();

        uint32_t Ab = sb + (uint32_t)(t & 1) * STAGE;
        uint32_t Bb = Ab + 2 * ALIMB;
        #pragma unroll
        for (int kk = 0; kk < 2; kk++) {
            uint32_t ah[2][4], al[2][4];
            #pragma unroll
            for (int mi = 0; mi < 2; mi++) {
                uint32_t ad = Ab + (uint32_t)((mw*32 + mi*16 + (lane & 15)) * 80
                                             + (kk*2 + (lane >> 4)) * 16);
                ldsm_x4(ah[mi], ad);
                ldsm_x4(al[mi], ad + ALIMB);
            }
            #pragma unroll
            for (int nj = 0; nj < 4; nj++) {
                uint32_t bd = Bb + (uint32_t)((kk*16 + (lane & 15)) * 272
                                             + (nw*8 + nj*2 + (lane >> 4)) * 16);
                uint32_t rh[4], rl[4];
                ldsm_x4t(rh, bd);
                ldsm_x4t(rl, bd + BLIMB);
                #pragma unroll
                for (int mi = 0; mi < 2; mi++) {
                    mma_bf16(acc[mi][2*nj],   ah[mi], &rh[0]);
                    mma_bf16(acc[mi][2*nj+1], ah[mi], &rh[2]);
                }
                #pragma unroll
                for (int mi = 0; mi < 2; mi++) {
                    mma_bf16(acc[mi][2*nj],   al[mi], &rh[0]);
                    mma_bf16(acc[mi][2*nj+1], al[mi], &rh[2]);
                }
                #pragma unroll
                for (int mi = 0; mi < 2; mi++) {
                    mma_bf16(acc[mi][2*nj],   ah[mi], &rl[0]);
                    mma_bf16(acc[mi][2*nj+1], ah[mi], &rl[2]);
                }
            }
        }
        __syncthreads();
    }

    // ---- epilogue ----
    #pragma unroll
    for (int mi = 0; mi < 2; mi++) {
        #pragma unroll
        for (int ni = 0; ni < 8; ni++) {
            int r0 = blockIdx.y * 128 + mw * 32 + mi * 16 + (lane >> 2);
            int c  = blockIdx.x * 128 + nw * 64 + ni * 8 + (lane & 3) * 2;
            float2 bv = *(const float2*)(bias + c);
            #pragma unroll
            for (int half = 0; half < 2; half++) {
                int row = r0 + half * 8;
                float vx = acc[mi][ni][half * 2 + 0] + bv.x;
                float vy = acc[mi][ni][half * 2 + 1] + bv.y;
                size_t idx = (size_t)row * Ntot + c;
                if (epi == 1) {
                    vx = gelu_exact(vx);
                    vy = gelu_exact(vy);
                    uint32_t h, l;
                    split_pack(vx, vy, h, l);
                    *(uint32_t*)(Ch + idx) = h;
                    *(uint32_t*)(Cl + idx) = l;
                } else {
                    if (epi == 2) {
                        float2 r1 = *(const float2*)(res1 + idx);
                        float2 r2 = *(const float2*)(res2 + idx);
                        vx += r1.x + r2.x;
                        vy += r1.y + r2.y;
                    }
                    *(float2*)(C + idx) = make_float2(vx, vy);
                }
            }
        }
    }
}

// ---------------- block reduction helpers (blockDim.x == 256) ----------------
__device__ __forceinline__ float blockSum256(float v, float* sm) {
    #pragma unroll
    for (int o = 16; o; o >>= 1) v += __shfl_xor_sync(0xffffffffu, v, o);
    int t = threadIdx.x;
    __syncthreads();
    if ((t & 31) == 0) sm[t >> 5] = v;
    __syncthreads();
    if (t == 0) {
        float z = 0.f;
        #pragma unroll
        for (int i = 0; i < 8; i++) z += sm[i];
        sm[8] = z;
    }
    __syncthreads();
    return sm[8];
}
__device__ __forceinline__ float blockMax256(float v, float* sm) {
    #pragma unroll
    for (int o = 16; o; o >>= 1) v = fmaxf(v, __shfl_xor_sync(0xffffffffu, v, o));
    int t = threadIdx.x;
    __syncthreads();
    if ((t & 31) == 0) sm[t >> 5] = v;
    __syncthreads();
    if (t == 0) {
        float z = sm[0];
        #pragma unroll
        for (int i = 1; i < 8; i++) z = fmaxf(z, sm[i]);
        sm[8] = z;
    }
    __syncthreads();
    return sm[8];
}

// ---------------- LayerNorm over 1024; optional bf16 hi/lo plane output ----
__global__ void ln1024_k(const float* __restrict__ X, float* __restrict__ Y,
                         const float* __restrict__ g, const float* __restrict__ bta,
                         __nv_bfloat16* __restrict__ H, __nv_bfloat16* __restrict__ L)
{
    __shared__ float sm[9];
    size_t row = blockIdx.x;
    int t = threadIdx.x;
    const float* xr = X + row * 1024;
    float4 v = *(const float4*)(xr + t * 4);
    float s = v.x + v.y + v.z + v.w;
    float mean = blockSum256(s, sm) * (1.0f / 1024.0f);
    float dx = v.x - mean, dy = v.y - mean, dz = v.z - mean, dw = v.w - mean;
    float q = dx * dx + dy * dy + dz * dz + dw * dw;
    float var = blockSum256(q, sm) * (1.0f / 1024.0f);
    float rstd = rsqrtf(var + EPS_LN);
    int c = t * 4;
    float4 gg = *(const float4*)(g + c);
    float4 bb = *(const float4*)(bta + c);
    float4 o;
    o.x = dx * rstd * gg.x + bb.x;
    o.y = dy * rstd * gg.y + bb.y;
    o.z = dz * rstd * gg.z + bb.z;
    o.w = dw * rstd * gg.w + bb.w;
    *(float4*)(Y + row * 1024 + c) = o;
    if (H) {
        uint32_t h0, l0, h1, l1;
        split_pack(o.x, o.y, h0, l0);
        split_pack(o.z, o.w, h1, l1);
        *(uint2*)(H + row * 1024 + c) = make_uint2(h0, h1);
        *(uint2*)(L + row * 1024 + c) = make_uint2(l0, l1);
    }
}

// ---------------- phi feature map ----------------
__device__ __forceinline__ float phi_map(float x, float cc) {
    float z = -x * cc;
    float sp = (z > 20.0f) ? z : log1pf(expf(z));
    return sp / cc + x;
}

__global__ void phi_k(const float* __restrict__ T, float* __restrict__ P,
                      const float* __restrict__ Wg, const float* __restrict__ bg,
                      const float* __restrict__ gg, const float* __restrict__ betag,
                      const float* __restrict__ cptr)
{
    __shared__ float Ws[64 * 64];
    __shared__ float sbg[64], sgg[64], sbeta[64];
    int t = threadIdx.x;
    for (int i = t; i < 4096; i += 256) Ws[i] = Wg[i];
    if (t < 64) { sbg[t] = bg[t]; sgg[t] = gg[t]; sbeta[t] = betag[t]; }
    __syncthreads();

    float cc = fabsf(*cptr) + EPS_ATTN;
    int w = t >> 5, lane = t & 31;
    size_t row = (size_t)blockIdx.x * 8 + w;
    const float* tr = T + row * 64;
    float t0 = tr[lane], t1 = tr[32 + lane];

    float u0 = sbg[lane], u1 = sbg[32 + lane];
    #pragma unroll
    for (int dd = 0; dd < 32; dd++) {
        float a0 = __shfl_sync(0xffffffffu, t0, dd);
        float a1 = __shfl_sync(0xffffffffu, t1, dd);
        u0 += a0 * Ws[dd * 64 + lane]        + a1 * Ws[(dd + 32) * 64 + lane];
        u1 += a0 * Ws[dd * 64 + lane + 32]   + a1 * Ws[(dd + 32) * 64 + lane + 32];
    }
    float s = u0 + u1;
    #pragma unroll
    for (int o = 16; o; o >>= 1) s += __shfl_xor_sync(0xffffffffu, s, o);
    float mean = s * (1.0f / 64.0f);
    float d0 = u0 - mean, d1 = u1 - mean;
    float q = d0 * d0 + d1 * d1;
    #pragma unroll
    for (int o = 16; o; o >>= 1) q += __shfl_xor_sync(0xffffffffu, q, o);
    float rstd = rsqrtf(q * (1.0f / 64.0f) + EPS_LN);
    float x0 = d0 * rstd * sgg[lane]      + sbeta[lane];
    float x1 = d1 * rstd * sgg[32 + lane] + sbeta[32 + lane];
    P[row * 64 + lane]      = phi_map(x0, cc);
    P[row * 64 + 32 + lane] = phi_map(x1, cc);
}

// ---------------- misc ----------------
__global__ void zero_k(float* __restrict__ p, int n) {
    int i = blockIdx.x * 256 + threadIdx.x;
    if (i < n) p[i] = 0.0f;
}

__global__ void qgsum_k(const float* __restrict__ Q, float* __restrict__ qg)
{
    int j = blockIdx.x * 32 + threadIdx.x;
    int b = blockIdx.y;
    int l0 = blockIdx.z * 512 + threadIdx.y;
    const float* base = Q + ((size_t)b * LL + l0) * DD + j;
    float s = 0.f;
    #pragma unroll 8
    for (int i = 0; i < 64; i++) s += base[(size_t)i * 8 * DD];
    __shared__ float sm[8][32];
    sm[threadIdx.y][threadIdx.x] = s;
    __syncthreads();
    if (threadIdx.y == 0) {
        float tot = 0.f;
        #pragma unroll
        for (int r = 0; r < 8; r++) tot += sm[r][threadIdx.x];
        atomicAdd(&qg[b * DD + j], tot * (1.0f / 32768.0f));
    }
}

__global__ void scores_k(const float* __restrict__ Kln, const float* __restrict__ qg,
                         float* __restrict__ sc)
{
    int t = threadIdx.x, w = t >> 5, lane = t & 31;
    size_t r = (size_t)blockIdx.x * 8 + w;
    int h = (int)(r & 15);
    size_t bl = r >> 4;
    int l = (int)(bl & 4095);
    int b = (int)(bl >> 12);
    const float* kr = Kln + r * 64;
    const float* qr = qg + b * DD + h * 64;
    float s = kr[lane] * qr[lane] + kr[lane + 32] * qr[lane + 32];
    #pragma unroll
    for (int o = 16; o; o >>= 1) s += __shfl_xor_sync(0xffffffffu, s, o);
    if (lane == 0) sc[(size_t)(b * HH + h) * LL + l] = s;
}

__global__ void softmax_k(float* __restrict__ sc)
{
    __shared__ float sm[9];
    size_t base = (size_t)blockIdx.x * LL;
    int t = threadIdx.x;
    float v[16];
    const float4* p = (const float4*)(sc + base + t * 16);
    #pragma unroll
    for (int i = 0; i < 4; i++) {
        float4 a = p[i];
        v[i * 4 + 0] = a.x; v[i * 4 + 1] = a.y; v[i * 4 + 2] = a.z; v[i * 4 + 3] = a.w;
    }
    float m = v[0];
    #pragma unroll
    for (int i = 1; i < 16; i++) m = fmaxf(m, v[i]);
    m = blockMax256(m, sm);
    float s = 0.f;
    #pragma unroll
    for (int i = 0; i < 16; i++) { v[i] = expf(v[i] - m); s += v[i]; }
    s = blockSum256(s, sm);
    float inv = (float)LL / s;
    float4* po = (float4*)(sc + base + t * 16);
    #pragma unroll
    for (int i = 0; i < 4; i++) {
        float4 a;
        a.x = v[i * 4 + 0] * inv; a.y = v[i * 4 + 1] * inv;
        a.z = v[i * 4 + 2] * inv; a.w = v[i * 4 + 3] * inv;
        po[i] = a;
    }
}

__global__ void kv_k(const float* __restrict__ PK, const float* __restrict__ Vln,
                     const float* __restrict__ alpha, float* __restrict__ KV,
                     float* __restrict__ Ksum)
{
    __shared__ float kk[16][64];
    __shared__ float vv[16][64];
    int bh = blockIdx.x;
    int b = bh >> 4, h = bh & 15;
    int t = threadIdx.x;
    int lr = t >> 4;
    int c4 = (t & 15) * 4;
    int r4 = lr * 4;
    float acc[4][4];
    float ks[4] = {0.f, 0.f, 0.f, 0.f};
    #pragma unroll
    for (int i = 0; i < 4; i++)
        #pragma unroll
        for (int j = 0; j < 4; j++) acc[i][j] = 0.f;

    const float* aB = alpha + (size_t)bh * LL;
    int lstart = blockIdx.y * 512;
    for (int lc = lstart; lc < lstart + 512; lc += 16) {
        int l = lc + lr;
        size_t r = ((size_t)(b * LL + l) * HH + h);
        float al = aB[l];
        float4 k4 = *(const float4*)(PK + r * 64 + c4);
        k4.x *= al; k4.y *= al; k4.z *= al; k4.w *= al;
        *(float4*)&kk[lr][c4] = k4;
        *(float4*)&vv[lr][c4] = *(const float4*)(Vln + r * 64 + c4);
        __syncthreads();
        #pragma unroll
        for (int q = 0; q < 16; q++) {
            float4 ka = *(const float4*)&kk[q][r4];
            float4 vb = *(const float4*)&vv[q][c4];
            acc[0][0] += ka.x * vb.x; acc[0][1] += ka.x * vb.y; acc[0][2] += ka.x * vb.z; acc[0][3] += ka.x * vb.w;
            acc[1][0] += ka.y * vb.x; acc[1][1] += ka.y * vb.y; acc[1][2] += ka.y * vb.z; acc[1][3] += ka.y * vb.w;
            acc[2][0] += ka.z * vb.x; acc[2][1] += ka.z * vb.y; acc[2][2] += ka.z * vb.z; acc[2][3] += ka.z * vb.w;
            acc[3][0] += ka.w * vb.x; acc[3][1] += ka.w * vb.y; acc[3][2] += ka.w * vb.z; acc[3][3] += ka.w * vb.w;
            if (c4 == 0) { ks[0] += ka.x; ks[1] += ka.y; ks[2] += ka.z; ks[3] += ka.w; }
        }
        __syncthreads();
    }
    float* KVb = KV + (size_t)bh * 4096;
    #pragma unroll
    for (int i = 0; i < 4; i++)
        #pragma unroll
        for (int j = 0; j < 4; j++)
            atomicAdd(&KVb[(r4 + i) * 64 + c4 + j], acc[i][j]);
    if (c4 == 0) {
        #pragma unroll
        for (int i = 0; i < 4; i++) atomicAdd(&Ksum[bh * 64 + r4 + i], ks[i]);
    }
}

__global__ void out_k(const float* __restrict__ PQ, const float* __restrict__ KV,
                      const float* __restrict__ Ksum, float* __restrict__ O)
{
    __shared__ float KVs[64 * 64];
    __shared__ float Ks[64];
    int bh = blockIdx.x;
    int b = bh >> 4, h = bh & 15;
    int t = threadIdx.x, w = t >> 5, lane = t & 31;
    const float* KVg = KV + (size_t)bh * 4096;
    for (int i = t; i < 1024; i += 256)
        *(float4*)&KVs[i * 4] = *(const float4*)&KVg[i * 4];
    if (t < 64) Ks[t] = Ksum[bh * 64 + t];
    __syncthreads();

    int l0 = blockIdx.y * 8 + w;
    for (int it = 0; it < 64; it++) {
        int l = l0 + it * 64;
        size_t r = ((size_t)(b * LL + l) * HH + h);
        const float* q = PQ + r * 64;
        float q0 = q[lane], q1 = q[lane + 32];
        float dpart = q0 * Ks[lane] + q1 * Ks[lane + 32];
        #pragma unroll
        for (int o = 16; o; o >>= 1) dpart += __shfl_xor_sync(0xffffffffu, dpart, o);
        float n0 = 0.f, n1 = 0.f;
        #pragma unroll
        for (int dd = 0; dd < 32; dd++) {
            float a0 = __shfl_sync(0xffffffffu, q0, dd);
            float a1 = __shfl_sync(0xffffffffu, q1, dd);
            n0 += a0 * KVs[dd * 64 + lane]        + a1 * KVs[(dd + 32) * 64 + lane];
            n1 += a0 * KVs[dd * 64 + lane + 32]   + a1 * KVs[(dd + 32) * 64 + lane + 32];
        }
        float inv = 1.0f / (dpart + EPS_ATTN);
        O[r * 64 + lane]      = n0 * inv;
        O[r * 64 + lane + 32] = n1 * inv;
    }
}

// ---------------- launch ----------------
extern "C" void kernel_launch(void* const* d_in, const int* in_sizes, int n_in,
                              void* d_out, int out_size)
{
    (void)in_sizes; (void)n_in; (void)out_size;
    const float* x     = (const float*)d_in[0];
    const float* WQ    = (const float*)d_in[1];
    const float* bQ    = (const float*)d_in[2];
    const float* gQ    = (const float*)d_in[3];
    const float* betaQ = (const float*)d_in[4];
    const float* WK    = (const float*)d_in[5];
    const float* bK    = (const float*)d_in[6];
    const float* gK    = (const float*)d_in[7];
    const float* betaK = (const float*)d_in[8];
    const float* WV    = (const float*)d_in[9];
    const float* bV    = (const float*)d_in[10];
    const float* gV    = (const float*)d_in[11];
    const float* betaV = (const float*)d_in[12];
    const float* Wg    = (const float*)d_in[13];
    const float* bg    = (const float*)d_in[14];
    const float* gg    = (const float*)d_in[15];
    const float* betag = (const float*)d_in[16];
    const float* cpt   = (const float*)d_in[17];
    const float* g_an  = (const float*)d_in[18];
    const float* b_an  = (const float*)d_in[19];
    const float* W1    = (const float*)d_in[20];
    const float* b1    = (const float*)d_in[21];
    const float* W2    = (const float*)d_in[22];
    const float* b2    = (const float*)d_in[23];
    float* out = (float*)d_out;

    float *bufQ, *bufK, *bufV, *bufPQ, *bufPK, *bufO, *bufA;
    float *qg, *alpha, *KV, *Ksum;
    __nv_bfloat16 *xh, *xl, *Aph, *Apl, *Hph, *Hpl;
    __nv_bfloat16 *WQh, *WQl, *WKh, *WKl, *WVh, *WVl, *W1h, *W1l, *W2h, *W2l;
    cudaGetSymbolAddress((void**)&bufQ,  g_bufQ);
    cudaGetSymbolAddress((void**)&bufK,  g_bufK);
    cudaGetSymbolAddress((void**)&bufV,  g_bufV);
    cudaGetSymbolAddress((void**)&bufPQ, g_bufPQ);
    cudaGetSymbolAddress((void**)&bufPK, g_bufPK);
    cudaGetSymbolAddress((void**)&bufO,  g_bufO);
    cudaGetSymbolAddress((void**)&bufA,  g_bufA);
    cudaGetSymbolAddress((void**)&qg,    g_qg);
    cudaGetSymbolAddress((void**)&alpha, g_alpha);
    cudaGetSymbolAddress((void**)&KV,    g_KV);
    cudaGetSymbolAddress((void**)&Ksum,  g_Ksum);
    cudaGetSymbolAddress((void**)&xh,  g_xh);  cudaGetSymbolAddress((void**)&xl,  g_xl);
    cudaGetSymbolAddress((void**)&Aph, g_Ah);  cudaGetSymbolAddress((void**)&Apl, g_Al);
    cudaGetSymbolAddress((void**)&Hph, g_Hh);  cudaGetSymbolAddress((void**)&Hpl, g_Hl);
    cudaGetSymbolAddress((void**)&WQh, g_WQh); cudaGetSymbolAddress((void**)&WQl, g_WQl);
    cudaGetSymbolAddress((void**)&WKh, g_WKh); cudaGetSymbolAddress((void**)&WKl, g_WKl);
    cudaGetSymbolAddress((void**)&WVh, g_WVh); cudaGetSymbolAddress((void**)&WVl, g_WVl);
    cudaGetSymbolAddress((void**)&W1h, g_W1h); cudaGetSymbolAddress((void**)&W1l, g_W1l);
    cudaGetSymbolAddress((void**)&W2h, g_W2h); cudaGetSymbolAddress((void**)&W2l, g_W2l);

    cudaFuncSetAttribute(tc_gemm_k, cudaFuncAttributeMaxDynamicSharedMemorySize, SMEMB);

    // ---- pre-split inputs & weights to bf16 hi/lo planes ----
    split_k<<<(size_t)NR*DD/1024, 256>>>(x,  xh,  xl);
    split_k<<<(size_t)DD*DD/1024, 256>>>(WQ, WQh, WQl);
    split_k<<<(size_t)DD*DD/1024, 256>>>(WK, WKh, WKl);
    split_k<<<(size_t)DD*DD/1024, 256>>>(WV, WVh, WVl);
    split_k<<<(size_t)DD*MM/1024, 256>>>(W1, W1h, W1l);
    split_k<<<(size_t)MM*DD/1024, 256>>>(W2, W2h, W2l);

    dim3 gq(DD / 128, NR / 128);          // (8,128)
    tc_gemm_k<<<gq, 256, SMEMB>>>(xh, xl, WQh, WQl, bQ, nullptr, nullptr, bufQ, nullptr, nullptr, DD, DD, 0);
    tc_gemm_k<<<gq, 256, SMEMB>>>(xh, xl, WKh, WKl, bK, nullptr, nullptr, bufK, nullptr, nullptr, DD, DD, 0);
    tc_gemm_k<<<gq, 256, SMEMB>>>(xh, xl, WVh, WVl, bV, nullptr, nullptr, bufV, nullptr, nullptr, DD, DD, 0);

    ln1024_k<<<NR, 256>>>(bufQ, bufQ, gQ, betaQ, nullptr, nullptr);
    ln1024_k<<<NR, 256>>>(bufK, bufK, gK, betaK, nullptr, nullptr);
    ln1024_k<<<NR, 256>>>(bufV, bufV, gV, betaV, nullptr, nullptr);

    phi_k<<<NRH / 8, 256>>>(bufQ, bufPQ, Wg, bg, gg, betag, cpt);
    phi_k<<<NRH / 8, 256>>>(bufK, bufPK, Wg, bg, gg, betag, cpt);

    zero_k<<<(BB * DD + 255) / 256, 256>>>(qg, BB * DD);
    qgsum_k<<<dim3(DD / 32, BB, LL / 512), dim3(32, 8)>>>(bufQ, qg);

    scores_k<<<NRH / 8, 256>>>(bufK, qg, alpha);
    softmax_k<<<BB * HH, 256>>>(alpha);

    zero_k<<<(BB * HH * DH * DH + 255) / 256, 256>>>(KV, BB * HH * DH * DH);
    zero_k<<<(BB * HH * DH + 255) / 256, 256>>>(Ksum, BB * HH * DH);
    kv_k<<<dim3(BB * HH, 8), 256>>>(bufPK, bufV, alpha, KV, Ksum);

    out_k<<<dim3(BB * HH, 8), 256>>>(bufPQ, KV, Ksum, bufO);
    // post-attn LN: fp32 out (residual) + bf16 hi/lo planes (GEMM1 operand)
    ln1024_k<<<NR, 256>>>(bufO, bufA, g_an, b_an, Aph, Apl);

    // MLP: GEMM1 writes GELU output directly as bf16 hi/lo planes
    tc_gemm_k<<<dim3(MM / 128, NR / 128), 256, SMEMB>>>(
        Aph, Apl, W1h, W1l, b1, nullptr, nullptr, nullptr, Hph, Hpl, MM, DD, 1);
    tc_gemm_k<<<dim3(DD / 128, NR / 128), 256, SMEMB>>>(
        Hph, Hpl, W2h, W2l, b2, bufA, x, out, nullptr, nullptr, DD, MM, 2);
}